// round 1
// baseline (speedup 1.0000x reference)
#include <cuda_runtime.h>
#include <cuda_bf16.h>
#include <cstdint>

// Problem constants
#define Bsz 64
#define Tsz 512
#define Isz 512
#define Hsz 512

// ---------------------------------------------------------------------------
// Static device scratch (no runtime allocation allowed)
// ---------------------------------------------------------------------------
// xproj[d][t][b][h] : input projections + bias, both directions. 2*512*64*512 fl
__device__ float g_xproj[2u * Tsz * Bsz * Hsz];

// grid barrier state (monotonic counter, reset by a kernel each launch)
__device__ unsigned g_count;

__global__ void reset_bar_kernel() { g_count = 0; }

// ---------------------------------------------------------------------------
// Phase 1: xproj[d][t][b][h] = sum_i x[b][t][i] * Wx_d[h][i] + bias_d[h]
// Tiled 64x64 SGEMM, K=512, with register prefetch.
// grid: (H/64=8, T=512, 2)  block: 256
// ---------------------------------------------------------------------------
__global__ void __launch_bounds__(256) xproj_gemm_kernel(
    const float* __restrict__ x,
    const float* __restrict__ Wf, const float* __restrict__ bf,
    const float* __restrict__ Wb, const float* __restrict__ bb)
{
    const int d  = blockIdx.z;
    const float* __restrict__ W    = d ? Wb : Wf;
    const float* __restrict__ bias = d ? bb : bf;
    const int t  = blockIdx.y;
    const int n0 = blockIdx.x * 64;

    __shared__ float sa[16][68];   // [k][row(b)]
    __shared__ float sb[16][68];   // [k][col(h)]

    const int tid  = threadIdx.x;
    const int lrow = tid >> 2;          // 0..63
    const int lk   = (tid & 3) * 4;     // 0,4,8,12

    const float* aptr = x + ((size_t)lrow * Tsz + t) * Isz + lk;   // row b=lrow, this t
    const float* bptr = W + (size_t)(n0 + lrow) * Isz + lk;        // row h=n0+lrow

    float4 ra = *(const float4*)aptr;
    float4 rb = *(const float4*)bptr;

    const int tx = tid & 15;
    const int ty = tid >> 4;

    float acc[4][4];
#pragma unroll
    for (int i = 0; i < 4; i++)
#pragma unroll
        for (int j = 0; j < 4; j++) acc[i][j] = 0.0f;

    for (int k0 = 0; k0 < Isz; k0 += 16) {
        __syncthreads();
        sa[lk + 0][lrow] = ra.x; sa[lk + 1][lrow] = ra.y;
        sa[lk + 2][lrow] = ra.z; sa[lk + 3][lrow] = ra.w;
        sb[lk + 0][lrow] = rb.x; sb[lk + 1][lrow] = rb.y;
        sb[lk + 2][lrow] = rb.z; sb[lk + 3][lrow] = rb.w;
        __syncthreads();

        if (k0 + 16 < Isz) {
            ra = *(const float4*)(aptr + k0 + 16);
            rb = *(const float4*)(bptr + k0 + 16);
        }

#pragma unroll
        for (int kk = 0; kk < 16; kk++) {
            float4 av = *(const float4*)&sa[kk][ty * 4];
            float4 bv = *(const float4*)&sb[kk][tx * 4];
            float a[4] = {av.x, av.y, av.z, av.w};
            float b[4] = {bv.x, bv.y, bv.z, bv.w};
#pragma unroll
            for (int i = 0; i < 4; i++)
#pragma unroll
                for (int j = 0; j < 4; j++)
                    acc[i][j] += a[i] * b[j];
        }
    }

    float4 bv4 = *(const float4*)(bias + n0 + tx * 4);
    const float badd[4] = {bv4.x, bv4.y, bv4.z, bv4.w};

#pragma unroll
    for (int i = 0; i < 4; i++) {
        int row = ty * 4 + i;   // b index
        float4 o;
        o.x = acc[i][0] + badd[0];
        o.y = acc[i][1] + badd[1];
        o.z = acc[i][2] + badd[2];
        o.w = acc[i][3] + badd[3];
        size_t idx = (((size_t)d * Tsz + t) * Bsz + row) * Hsz + n0 + tx * 4;
        *(float4*)(g_xproj + idx) = o;
    }
}

// ---------------------------------------------------------------------------
// Phase 2: persistent bidirectional scan.
// grid: 128 CTAs (64 per direction, 8 H-columns each), block 256, 1 wave.
// h state lives in y itself: y[b][t][dir*512 + h].
// Per step: stage prev-h (64x512, [b][k] pitch 516) in smem, fp32 dot, tanh,
// scalar store to y, grid barrier.
// ---------------------------------------------------------------------------
#define SCAN_CTAS 128
#define HSM_PITCH 516   // 516 % 32 == 4 -> conflict-free LDS.128 per 8-lane phase

__global__ void __launch_bounds__(256) scan_kernel(
    const float* __restrict__ h0f, const float* __restrict__ h0b,
    const float* __restrict__ Whf, const float* __restrict__ Whb,
    float* __restrict__ y)
{
    extern __shared__ float sm[];
    float* ws  = sm;                // [8][512]  Wh rows for this CTA's columns
    float* hsm = sm + 8 * 512;      // [64][HSM_PITCH]  prev h, [b][k]

    const int cta = blockIdx.x;
    const int dir = cta >> 6;       // 0 fwd, 1 bwd
    const int seg = cta & 63;
    const int jg0 = seg << 3;       // first of 8 owned columns

    const float* __restrict__ Wh = dir ? Whb : Whf;
    const float* __restrict__ h0 = dir ? h0b : h0f;

    const int tid = threadIdx.x;

    // Load this CTA's 8 Wh rows once (8 x 512 floats)
    for (int idx = tid; idx < 8 * 128; idx += 256) {
        int r = idx >> 7;
        int c = (idx & 127) * 4;
        *(float4*)&ws[r * 512 + c] =
            *(const float4*)(Wh + (size_t)(jg0 + r) * Hsz + c);
    }

    const int w    = tid >> 5;
    const int lane = tid & 31;
    const int jl0  = (w & 3) * 2;            // local column pair {0,2,4,6}
    const int b    = ((w >> 2) << 5) + lane; // batch row

    const float* wp0  = ws + jl0 * 512;
    const float* wp1  = wp0 + 512;
    const float* hrow = hsm + b * HSM_PITCH;

    unsigned target = 0;

    for (int step = 0; step < Tsz; step++) {
        const int t = dir ? (Tsz - 1 - step) : step;

        // ---- stage previous h into smem: hsm[b][k] ----
        const float* src;
        int rstride;
        if (step == 0) {
            src = h0;                      // [b][k], pitch 512
            rstride = Hsz;
        } else {
            int tp = dir ? (t + 1) : (t - 1);
            src = y + (size_t)tp * (2 * Hsz) + (dir << 9);  // row b at stride T*2H
            rstride = Tsz * 2 * Hsz;
        }
        for (int idx = tid; idx < 64 * 128; idx += 256) {
            int r = idx >> 7;
            int c = (idx & 127) * 4;
            float4 v = *(const float4*)(src + (size_t)r * rstride + c);
            *(float4*)&hsm[r * HSM_PITCH + c] = v;
        }
        __syncthreads();

        // xproj values (loaded early, consumed after the dot loop)
        const float* xp = g_xproj + (((size_t)dir * Tsz + t) * Bsz + b) * Hsz + jg0;
        float xpv0 = xp[jl0];
        float xpv1 = xp[jl0 + 1];

        float acc0 = 0.0f, acc1 = 0.0f;
#pragma unroll 8
        for (int k = 0; k < Hsz; k += 4) {
            float4 h4 = *(const float4*)(hrow + k);
            float4 wa = *(const float4*)(wp0 + k);
            float4 wb = *(const float4*)(wp1 + k);
            acc0 += h4.x * wa.x; acc1 += h4.x * wb.x;
            acc0 += h4.y * wa.y; acc1 += h4.y * wb.y;
            acc0 += h4.z * wa.z; acc1 += h4.z * wb.z;
            acc0 += h4.w * wa.w; acc1 += h4.w * wb.w;
        }

        float* yp = y + ((size_t)b * Tsz + t) * (2 * Hsz) + (dir << 9) + jg0;
        yp[jl0]     = tanhf(acc0 + xpv0);
        yp[jl0 + 1] = tanhf(acc1 + xpv1);

        // ---- grid barrier (monotonic counter, no reset race) ----
        __syncthreads();
        target += SCAN_CTAS;
        if (tid == 0) {
            __threadfence();
            unsigned v = atomicAdd(&g_count, 1u) + 1u;
            if (v != target) {
                volatile unsigned* vc = &g_count;
                while (*vc < target) { }
            }
            __threadfence();
        }
        __syncthreads();
    }
}

// ---------------------------------------------------------------------------
// Tail: extract hT_f = hs_f[T-1], hT_b = hs_b[t=0] from y into output tail.
// out layout: y (B,T,2H) | hT_f (B,H) | hT_b (B,H)
// ---------------------------------------------------------------------------
__global__ void tail_kernel(float* __restrict__ out)
{
    const int b = blockIdx.x;
    const int k = threadIdx.x;
    const float* y = out;
    const size_t yN = (size_t)Bsz * Tsz * 2 * Hsz;
    out[yN + (size_t)b * Hsz + k] =
        y[((size_t)b * Tsz + (Tsz - 1)) * (2 * Hsz) + k];
    out[yN + (size_t)Bsz * Hsz + (size_t)b * Hsz + k] =
        y[((size_t)b * Tsz) * (2 * Hsz) + Hsz + k];
}

// ---------------------------------------------------------------------------
// kernel_launch
// Inputs (metadata order):
//  0 x (B,T,I) 1 h0_f (B,H) 2 h0_b (B,H)
//  3 Wxf_w (H,I) 4 Wxf_b (H) 5 Whf_w (H,H)
//  6 Wxb_w (H,I) 7 Wxb_b (H) 8 Whb_w (H,H)
// ---------------------------------------------------------------------------
extern "C" void kernel_launch(void* const* d_in, const int* in_sizes, int n_in,
                              void* d_out, int out_size)
{
    const float* x     = (const float*)d_in[0];
    const float* h0f   = (const float*)d_in[1];
    const float* h0b   = (const float*)d_in[2];
    const float* Wxf_w = (const float*)d_in[3];
    const float* Wxf_b = (const float*)d_in[4];
    const float* Whf_w = (const float*)d_in[5];
    const float* Wxb_w = (const float*)d_in[6];
    const float* Wxb_b = (const float*)d_in[7];
    const float* Whb_w = (const float*)d_in[8];
    float* out = (float*)d_out;

    // dynamic smem for the scan kernel: 8*512 + 64*516 floats
    const int scan_smem = (8 * 512 + 64 * HSM_PITCH) * (int)sizeof(float);
    cudaFuncSetAttribute(scan_kernel,
                         cudaFuncAttributeMaxDynamicSharedMemorySize, scan_smem);

    reset_bar_kernel<<<1, 1>>>();

    dim3 ggrid(Hsz / 64, Tsz, 2);
    xproj_gemm_kernel<<<ggrid, 256>>>(x, Wxf_w, Wxf_b, Wxb_w, Wxb_b);

    scan_kernel<<<SCAN_CTAS, 256, scan_smem>>>(h0f, h0b, Whf_w, Whb_w, out);

    tail_kernel<<<Bsz, Hsz>>>(out);
}

// round 3
// speedup vs baseline: 1.8571x; 1.8571x over previous
#include <cuda_runtime.h>
#include <cuda_bf16.h>
#include <cstdint>

#define Bsz 64
#define Tsz 512
#define Isz 512
#define Hsz 512

// ---------------------------------------------------------------------------
// Static device scratch
// ---------------------------------------------------------------------------
__device__ float g_xproj[2u * Tsz * Bsz * Hsz];   // [d][t][b][h]
__device__ unsigned g_count;

__global__ void reset_bar_kernel() { g_count = 0; }

// ---------------------------------------------------------------------------
// Phase 1: xproj = x @ Wx^T + b.  M=(b,t)=32768, N=512, K=512, per dir.
// 128x128 CTA tile, 8x8 micro-tile (split halves), BK=8, reg prefetch.
// grid (4, 256, 2), block 256.
// ---------------------------------------------------------------------------
__global__ void __launch_bounds__(256, 2) xproj_gemm_kernel(
    const float* __restrict__ x,
    const float* __restrict__ Wf, const float* __restrict__ bf,
    const float* __restrict__ Wb, const float* __restrict__ bb)
{
    const int d = blockIdx.z;
    const float* __restrict__ W    = d ? Wb : Wf;
    const float* __restrict__ bias = d ? bb : bf;

    const int mt = blockIdx.y << 7;       // 0..32640, 128-row M tile
    const int b  = mt >> 9;               // batch (tiles never straddle b)
    const int t0 = mt & 511;
    const int n0 = blockIdx.x << 7;

    __shared__ float sA[8][132];
    __shared__ float sB[8][132];

    const int tid = threadIdx.x;
    const int r  = tid >> 1;              // 0..127
    const int cc = (tid & 1) * 4;         // 0 or 4

    const float* ap = x + ((size_t)(b * Tsz + t0 + r)) * Isz + cc;
    const float* bp = W + ((size_t)(n0 + r)) * Isz + cc;

    float4 ra = *(const float4*)ap;
    float4 rb = *(const float4*)bp;

    const int tr = tid >> 4;              // 0..15
    const int tc = tid & 15;              // 0..15

    float acc[8][8];
#pragma unroll
    for (int i = 0; i < 8; i++)
#pragma unroll
        for (int j = 0; j < 8; j++) acc[i][j] = 0.0f;

    for (int k0 = 0; k0 < Isz; k0 += 8) {
        __syncthreads();
        sA[cc + 0][r] = ra.x; sA[cc + 1][r] = ra.y;
        sA[cc + 2][r] = ra.z; sA[cc + 3][r] = ra.w;
        sB[cc + 0][r] = rb.x; sB[cc + 1][r] = rb.y;
        sB[cc + 2][r] = rb.z; sB[cc + 3][r] = rb.w;
        __syncthreads();

        if (k0 + 8 < Isz) {
            ra = *(const float4*)(ap + k0 + 8);
            rb = *(const float4*)(bp + k0 + 8);
        }

#pragma unroll
        for (int k = 0; k < 8; k++) {
            float4 a0 = *(const float4*)&sA[k][tr * 4];
            float4 a1 = *(const float4*)&sA[k][64 + tr * 4];
            float4 b0 = *(const float4*)&sB[k][tc * 4];
            float4 b1 = *(const float4*)&sB[k][64 + tc * 4];
            float am[8] = {a0.x, a0.y, a0.z, a0.w, a1.x, a1.y, a1.z, a1.w};
            float bn[8] = {b0.x, b0.y, b0.z, b0.w, b1.x, b1.y, b1.z, b1.w};
#pragma unroll
            for (int i = 0; i < 8; i++)
#pragma unroll
                for (int j = 0; j < 8; j++)
                    acc[i][j] += am[i] * bn[j];
        }
    }

    float4 bias0 = *(const float4*)(bias + n0 + tc * 4);
    float4 bias1 = *(const float4*)(bias + n0 + 64 + tc * 4);

#pragma unroll
    for (int mi = 0; mi < 8; mi++) {
        int rloc = (mi < 4) ? (tr * 4 + mi) : (64 + tr * 4 + (mi - 4));
        int t = t0 + rloc;
        float* op = g_xproj + (((size_t)d * Tsz + t) * Bsz + b) * Hsz + n0;
        float4 o0, o1;
        o0.x = acc[mi][0] + bias0.x; o0.y = acc[mi][1] + bias0.y;
        o0.z = acc[mi][2] + bias0.z; o0.w = acc[mi][3] + bias0.w;
        o1.x = acc[mi][4] + bias1.x; o1.y = acc[mi][5] + bias1.y;
        o1.z = acc[mi][6] + bias1.z; o1.w = acc[mi][7] + bias1.w;
        *(float4*)(op + tc * 4)      = o0;
        *(float4*)(op + 64 + tc * 4) = o1;
    }
}

// ---------------------------------------------------------------------------
// Phase 2: persistent bidirectional scan, 128 CTAs (one wave), block 256.
// CTA = (dir, 8 columns). Thread = (4 cols x 4 batches) over a K-chunk of 64,
// butterfly-reduced over the 8 K-chunk lanes of each warp.
//
// smem layouts (floats), chosen so each LDS.128 phase (8 lanes, kc=0..7)
// hits 8 distinct 16B bank groups (chunk strides are ODD in 16B units):
//   ws [kc][j][kk] : chunk stride 548  (=137 units, odd)
//   hsm[kc][b][kk] : chunk stride 4356 (=1089 units, odd), row stride 68
// ---------------------------------------------------------------------------
#define SCAN_CTAS 128
#define WCH 548
#define HCH 4356

__global__ void __launch_bounds__(256) scan_kernel(
    const float* __restrict__ h0f, const float* __restrict__ h0b,
    const float* __restrict__ Whf, const float* __restrict__ Whb,
    float* __restrict__ y)
{
    extern __shared__ float sm[];
    float* ws  = sm;              // 8 * 548
    float* hsm = sm + 8 * WCH;    // 8 * 4356

    const int cta = blockIdx.x;
    const int dir = cta >> 6;
    const int seg = cta & 63;
    const int jg0 = seg << 3;     // 8 owned columns

    const float* __restrict__ Wh = dir ? Whb : Whf;
    const float* __restrict__ h0 = dir ? h0b : h0f;

    const int tid = threadIdx.x;

    // Load Wh rows for owned columns into chunked layout (once).
    for (int idx = tid; idx < 8 * 128; idx += 256) {
        int j  = idx >> 7;
        int c  = idx & 127;
        int kc = c >> 4;
        int kk = (c & 15) * 4;
        float4 v = *(const float4*)(Wh + (size_t)(jg0 + j) * Hsz + c * 4);
        *(float4*)&ws[kc * WCH + j * 68 + kk] = v;
    }

    const int lane = tid & 31;
    const int w    = tid >> 5;
    const int kc   = lane & 7;         // K-chunk id
    const int s    = lane >> 3;        // 0..3
    const int jt   = s & 1;            // col-tile {0,1} -> cols jt*4..+3
    const int bt   = w * 2 + (s >> 1); // batch-tile 0..15 -> b bt*4..+3

    const float* hp = hsm + kc * HCH + (bt * 4) * 68;
    const float* wp = ws  + kc * WCH + (jt * 4) * 68;

    // this thread's 2 final outputs (after reduction)
    const int o0    = 2 * kc;          // 0..14 even
    const int oi    = o0 >> 2;         // batch within tile
    const int oj    = o0 & 3;          // col within tile (0 or 2)
    const int b_out = bt * 4 + oi;
    const int col   = jg0 + jt * 4 + oj;

    unsigned target = 0;

    for (int step = 0; step < Tsz; step++) {
        const int t = dir ? (Tsz - 1 - step) : step;

        // ---- stage h(t-1) into chunked smem ----
        const float* src;
        size_t rstride;
        if (step == 0) {
            src = h0; rstride = Hsz;
        } else {
            int tp = dir ? (t + 1) : (t - 1);
            src = y + (size_t)tp * (2 * Hsz) + ((size_t)dir << 9);
            rstride = (size_t)Tsz * 2 * Hsz;
        }
        for (int idx = tid; idx < 64 * 128; idx += 256) {
            int rr  = idx >> 7;
            int c   = idx & 127;
            int kc2 = c >> 4;
            int kk2 = (c & 15) * 4;
            float4 v = __ldcg((const float4*)(src + rr * rstride + c * 4));
            *(float4*)&hsm[kc2 * HCH + rr * 68 + kk2] = v;
        }

        // xproj for this thread's outputs (independent of h -> issue early)
        const float2 xp = __ldcg((const float2*)(
            g_xproj + (((size_t)dir * Tsz + t) * Bsz + b_out) * Hsz + col));

        __syncthreads();

        // ---- 4x4 register-tile partial dot over K-chunk of 64 ----
        float acc[4][4];
#pragma unroll
        for (int i = 0; i < 4; i++)
#pragma unroll
            for (int j = 0; j < 4; j++) acc[i][j] = 0.0f;

#pragma unroll 4
        for (int kk = 0; kk < 64; kk += 4) {
            float4 h0v = *(const float4*)(hp + 0 * 68 + kk);
            float4 h1v = *(const float4*)(hp + 1 * 68 + kk);
            float4 h2v = *(const float4*)(hp + 2 * 68 + kk);
            float4 h3v = *(const float4*)(hp + 3 * 68 + kk);
            float4 w0v = *(const float4*)(wp + 0 * 68 + kk);
            float4 w1v = *(const float4*)(wp + 1 * 68 + kk);
            float4 w2v = *(const float4*)(wp + 2 * 68 + kk);
            float4 w3v = *(const float4*)(wp + 3 * 68 + kk);
            float hx[4][4] = {{h0v.x, h0v.y, h0v.z, h0v.w},
                              {h1v.x, h1v.y, h1v.z, h1v.w},
                              {h2v.x, h2v.y, h2v.z, h2v.w},
                              {h3v.x, h3v.y, h3v.z, h3v.w}};
            float wx[4][4] = {{w0v.x, w0v.y, w0v.z, w0v.w},
                              {w1v.x, w1v.y, w1v.z, w1v.w},
                              {w2v.x, w2v.y, w2v.z, w2v.w},
                              {w3v.x, w3v.y, w3v.z, w3v.w}};
#pragma unroll
            for (int i = 0; i < 4; i++)
#pragma unroll
                for (int j = 0; j < 4; j++)
#pragma unroll
                    for (int q = 0; q < 4; q++)
                        acc[i][j] += hx[i][q] * wx[j][q];
        }

        // ---- butterfly reduce over the 8 kc lanes ----
#pragma unroll
        for (int m = 1; m < 8; m <<= 1)
#pragma unroll
            for (int i = 0; i < 4; i++)
#pragma unroll
                for (int j = 0; j < 4; j++)
                    acc[i][j] += __shfl_xor_sync(0xffffffffu, acc[i][j], m);

        // select this lane's 2 outputs (static unroll avoids local-mem)
        float v0 = 0.0f, v1 = 0.0f;
#pragma unroll
        for (int i = 0; i < 4; i++)
#pragma unroll
            for (int j = 0; j < 4; j += 2)
                if (oi == i && oj == j) { v0 = acc[i][j]; v1 = acc[i][j + 1]; }

        float r0 = tanhf(v0 + xp.x);
        float r1 = tanhf(v1 + xp.y);

        float* yp = y + ((size_t)b_out * Tsz + t) * (2 * Hsz) + (dir << 9) + col;
        *(float2*)yp = make_float2(r0, r1);

        // ---- grid barrier (monotonic counter) ----
        __syncthreads();
        target += SCAN_CTAS;
        if (tid == 0) {
            __threadfence();
            unsigned v = atomicAdd(&g_count, 1u) + 1u;
            if (v != target) {
                volatile unsigned* vc = &g_count;
                while (*vc < target) { }
            }
            __threadfence();
        }
        __syncthreads();
    }
}

// ---------------------------------------------------------------------------
// Tail: hT_f = hs_f[T-1], hT_b = hs_b[t=0]
// ---------------------------------------------------------------------------
__global__ void tail_kernel(float* __restrict__ out)
{
    const int b = blockIdx.x;
    const int k = threadIdx.x;
    const float* y = out;
    const size_t yN = (size_t)Bsz * Tsz * 2 * Hsz;
    out[yN + (size_t)b * Hsz + k] =
        y[((size_t)b * Tsz + (Tsz - 1)) * (2 * Hsz) + k];
    out[yN + (size_t)Bsz * Hsz + (size_t)b * Hsz + k] =
        y[((size_t)b * Tsz) * (2 * Hsz) + Hsz + k];
}

// ---------------------------------------------------------------------------
extern "C" void kernel_launch(void* const* d_in, const int* in_sizes, int n_in,
                              void* d_out, int out_size)
{
    const float* x     = (const float*)d_in[0];
    const float* h0f   = (const float*)d_in[1];
    const float* h0b   = (const float*)d_in[2];
    const float* Wxf_w = (const float*)d_in[3];
    const float* Wxf_b = (const float*)d_in[4];
    const float* Whf_w = (const float*)d_in[5];
    const float* Wxb_w = (const float*)d_in[6];
    const float* Wxb_b = (const float*)d_in[7];
    const float* Whb_w = (const float*)d_in[8];
    float* out = (float*)d_out;

    const int scan_smem = (8 * WCH + 8 * HCH) * (int)sizeof(float);
    cudaFuncSetAttribute(scan_kernel,
                         cudaFuncAttributeMaxDynamicSharedMemorySize, scan_smem);

    reset_bar_kernel<<<1, 1>>>();

    dim3 ggrid(4, 256, 2);
    xproj_gemm_kernel<<<ggrid, 256>>>(x, Wxf_w, Wxf_b, Wxb_w, Wxb_b);

    scan_kernel<<<SCAN_CTAS, 256, scan_smem>>>(h0f, h0b, Whf_w, Whb_w, out);

    tail_kernel<<<Bsz, Hsz>>>(out);
}

// round 5
// speedup vs baseline: 2.4617x; 1.3256x over previous
#include <cuda_runtime.h>
#include <cuda_bf16.h>
#include <cstdint>

#define Bsz 64
#define Tsz 512
#define Isz 512
#define Hsz 512

// ---------------------------------------------------------------------------
// Static device scratch
// ---------------------------------------------------------------------------
__device__ float g_xproj[2u * Tsz * Bsz * Hsz];   // [d][t][b][h]
__device__ unsigned g_count;

__global__ void reset_bar_kernel() { g_count = 0; }

// ---------------------------------------------------------------------------
// Packed fp32x2 helpers (Blackwell FFMA2 path)
// ---------------------------------------------------------------------------
typedef unsigned long long ull;

__device__ __forceinline__ ull ffma2(ull a, ull b, ull c) {
    ull d;
    asm("fma.rn.f32x2 %0, %1, %2, %3;" : "=l"(d) : "l"(a), "l"(b), "l"(c));
    return d;
}
__device__ __forceinline__ ull pack2(float x) {
    ull d;
    asm("mov.b64 %0, {%1, %1};" : "=l"(d) : "f"(x));
    return d;
}
__device__ __forceinline__ float2 unpack2(ull a) {
    float2 r;
    asm("mov.b64 {%0, %1}, %2;" : "=f"(r.x), "=f"(r.y) : "l"(a));
    return r;
}

// ---------------------------------------------------------------------------
// Phase 1: xproj = x @ Wx^T + b.  M=32768, N=512, K=512, per dir.
// 128x128 CTA tile, 8x8 micro-tile via f32x2, BK=8, reg prefetch.
// grid (4, 256, 2), block 256.
// ---------------------------------------------------------------------------
__global__ void __launch_bounds__(256, 2) xproj_gemm_kernel(
    const float* __restrict__ x,
    const float* __restrict__ Wf, const float* __restrict__ bf,
    const float* __restrict__ Wb, const float* __restrict__ bb)
{
    const int d = blockIdx.z;
    const float* __restrict__ W    = d ? Wb : Wf;
    const float* __restrict__ bias = d ? bb : bf;

    const int mt = blockIdx.y << 7;
    const int b  = mt >> 9;
    const int t0 = mt & 511;
    const int n0 = blockIdx.x << 7;

    __shared__ float sA[8][132];
    __shared__ float sB[8][132];

    const int tid = threadIdx.x;
    const int r  = tid >> 1;
    const int cc = (tid & 1) * 4;

    const float* ap = x + ((size_t)(b * Tsz + t0 + r)) * Isz + cc;
    const float* bp = W + ((size_t)(n0 + r)) * Isz + cc;

    float4 ra = *(const float4*)ap;
    float4 rb = *(const float4*)bp;

    const int tr = tid >> 4;
    const int tc = tid & 15;

    ull acc2[8][4];
#pragma unroll
    for (int i = 0; i < 8; i++)
#pragma unroll
        for (int j = 0; j < 4; j++) acc2[i][j] = 0ull;

    for (int k0 = 0; k0 < Isz; k0 += 8) {
        __syncthreads();
        sA[cc + 0][r] = ra.x; sA[cc + 1][r] = ra.y;
        sA[cc + 2][r] = ra.z; sA[cc + 3][r] = ra.w;
        sB[cc + 0][r] = rb.x; sB[cc + 1][r] = rb.y;
        sB[cc + 2][r] = rb.z; sB[cc + 3][r] = rb.w;
        __syncthreads();

        if (k0 + 8 < Isz) {
            ra = *(const float4*)(ap + k0 + 8);
            rb = *(const float4*)(bp + k0 + 8);
        }

#pragma unroll
        for (int k = 0; k < 8; k++) {
            float4 a0 = *(const float4*)&sA[k][tr * 4];
            float4 a1 = *(const float4*)&sA[k][64 + tr * 4];
            ulonglong2 b0q = *(const ulonglong2*)&sB[k][tc * 4];
            ulonglong2 b1q = *(const ulonglong2*)&sB[k][64 + tc * 4];
            float am[8] = {a0.x, a0.y, a0.z, a0.w, a1.x, a1.y, a1.z, a1.w};
#pragma unroll
            for (int i = 0; i < 8; i++) {
                ull apk = pack2(am[i]);
                acc2[i][0] = ffma2(apk, b0q.x, acc2[i][0]);
                acc2[i][1] = ffma2(apk, b0q.y, acc2[i][1]);
                acc2[i][2] = ffma2(apk, b1q.x, acc2[i][2]);
                acc2[i][3] = ffma2(apk, b1q.y, acc2[i][3]);
            }
        }
    }

    float4 bias0 = *(const float4*)(bias + n0 + tc * 4);
    float4 bias1 = *(const float4*)(bias + n0 + 64 + tc * 4);

#pragma unroll
    for (int mi = 0; mi < 8; mi++) {
        int rloc = (mi < 4) ? (tr * 4 + mi) : (64 + tr * 4 + (mi - 4));
        int t = t0 + rloc;
        float* op = g_xproj + (((size_t)d * Tsz + t) * Bsz + b) * Hsz + n0;
        float2 p0 = unpack2(acc2[mi][0]);
        float2 p1 = unpack2(acc2[mi][1]);
        float2 p2 = unpack2(acc2[mi][2]);
        float2 p3 = unpack2(acc2[mi][3]);
        float4 o0, o1;
        o0.x = p0.x + bias0.x; o0.y = p0.y + bias0.y;
        o0.z = p1.x + bias0.z; o0.w = p1.y + bias0.w;
        o1.x = p2.x + bias1.x; o1.y = p2.y + bias1.y;
        o1.z = p3.x + bias1.z; o1.w = p3.y + bias1.w;
        *(float4*)(op + tc * 4)      = o0;
        *(float4*)(op + 64 + tc * 4) = o1;
    }
}

// ---------------------------------------------------------------------------
// Phase 2: persistent scan. 128 CTAs = (2 dir) x (8 batch-tiles) x (8 col-tiles)
// CTA owns 8 batches x 64 cols. W slice (64x512) resident in smem (chunked
// k-major), loaded once. Per step it stages only h[own 8 batches] (16 KB).
// Warp = 8-col tile; lane = one of 32 K-chunks (Kc=16); thread computes an
// 8b x 8c f32x2 register tile; 5-level jammed butterfly distributes results.
//
// smem (floats):
//   WS[kc][k'][c]  kc<32, k'<16, c<64   chunk stride 1028 (257 16B-units, odd)
//   HS[kc][b][kk]  kc<32, b<8,  kk<16   chunk stride 132  (33 units, odd)
// ---------------------------------------------------------------------------
#define SCAN_CTAS 128
#define WCH 1028
#define HCH 132

__global__ void __launch_bounds__(256) scan_kernel(
    const float* __restrict__ h0f, const float* __restrict__ h0b,
    const float* __restrict__ Whf, const float* __restrict__ Whb,
    float* __restrict__ y)
{
    extern __shared__ float sm[];
    float* WS = sm;               // 32 * 1028
    float* HS = sm + 32 * WCH;    // 32 * 132

    const int cta   = blockIdx.x;
    const int dir   = cta >> 6;
    const int btile = (cta >> 3) & 7;
    const int ctile = cta & 7;
    const int b0    = btile << 3;   // 8 batches
    const int cbase = ctile << 6;   // 64 cols

    const float* __restrict__ Wh = dir ? Whb : Whf;
    const float* __restrict__ h0 = dir ? h0b : h0f;

    const int tid = threadIdx.x;

    // ---- load W slice once, chunked k-major: WS[kc][k'][c] = Wh[cbase+c][kc*16+k']
    for (int i = tid; i < 64 * 128; i += 256) {
        int c  = i >> 7;
        int k4 = (i & 127) * 4;
        float4 v = *(const float4*)(Wh + (size_t)(cbase + c) * Hsz + k4);
        int kc = k4 >> 4, kk = k4 & 15;
        float* wsl = WS + kc * WCH + kk * 64 + c;
        wsl[0 * 64] = v.x; wsl[1 * 64] = v.y; wsl[2 * 64] = v.z; wsl[3 * 64] = v.w;
    }

    const int lane = tid & 31;
    const int w    = tid >> 5;
    const int kc   = lane;          // K-chunk
    const int c0   = w << 3;        // warp's local col base

    // final outputs of this lane after the halving butterfly:
    // o0 = 32*b0(lane)+16*b1+8*b2+4*b3+2*b4  (o = b_local*8 + c_local)
    const int o0 = ((lane & 1) << 5) | (((lane >> 1) & 1) << 4) |
                   (((lane >> 2) & 1) << 3) | (((lane >> 3) & 1) << 2) |
                   (((lane >> 4) & 1) << 1);
    const int b_out = b0 + (o0 >> 3);
    const int colg  = cbase + c0 + (o0 & 7);   // and colg+1

    unsigned target = 0;

    for (int step = 0; step < Tsz; step++) {
        const int t = dir ? (Tsz - 1 - step) : step;

        // ---- stage h(t-1)[b0..b0+8][:] into HS (16 KB) ----
        const float* src;
        size_t rstride;
        if (step == 0) {
            src = h0 + (size_t)b0 * Hsz; rstride = Hsz;
        } else {
            int tp = dir ? (t + 1) : (t - 1);
            src = y + ((size_t)b0 * Tsz + tp) * (2 * Hsz) + ((size_t)dir << 9);
            rstride = (size_t)Tsz * 2 * Hsz;
        }
        for (int i = tid; i < 1024; i += 256) {          // 8b x 128 float4
            int b  = i >> 7;
            int k  = (i & 127) * 4;
            float4 v = __ldcg((const float4*)(src + b * rstride + k));
            int kcx = k >> 4, kk = k & 15;
            *(float4*)&HS[kcx * HCH + b * 16 + kk] = v;
        }

        // xproj for this lane's two outputs (global, barrier-independent)
        const float2 xp = __ldcg((const float2*)(
            g_xproj + (((size_t)dir * Tsz + t) * Bsz + b_out) * Hsz + colg));

        __syncthreads();

        // ---- 8b x 8c f32x2 tile over this lane's K-chunk of 16 ----
        ull acc[8][4];
#pragma unroll
        for (int b = 0; b < 8; b++)
#pragma unroll
            for (int j = 0; j < 4; j++) acc[b][j] = 0ull;

        const float* hp = HS + kc * HCH;
        const float* wp = WS + kc * WCH + c0;

#pragma unroll
        for (int kk4 = 0; kk4 < 16; kk4 += 4) {
            float4 hv[8];
#pragma unroll
            for (int b = 0; b < 8; b++)
                hv[b] = *(const float4*)(hp + b * 16 + kk4);
#pragma unroll
            for (int k2 = 0; k2 < 4; k2++) {
                const float* wrow = wp + (kk4 + k2) * 64;
                ulonglong2 wa = *(const ulonglong2*)(wrow);
                ulonglong2 wb = *(const ulonglong2*)(wrow + 4);
#pragma unroll
                for (int b = 0; b < 8; b++) {
                    float hs = (k2 == 0) ? hv[b].x : (k2 == 1) ? hv[b].y
                             : (k2 == 2) ? hv[b].z : hv[b].w;
                    ull hpk = pack2(hs);
                    acc[b][0] = ffma2(hpk, wa.x, acc[b][0]);
                    acc[b][1] = ffma2(hpk, wa.y, acc[b][1]);
                    acc[b][2] = ffma2(hpk, wb.x, acc[b][2]);
                    acc[b][3] = ffma2(hpk, wb.y, acc[b][3]);
                }
            }
        }

        // ---- unpack to 64 scalars (o = b*8 + c) ----
        float v[64];
#pragma unroll
        for (int b = 0; b < 8; b++)
#pragma unroll
            for (int cp = 0; cp < 4; cp++) {
                float2 u = unpack2(acc[b][cp]);
                v[b * 8 + cp * 2]     = u.x;
                v[b * 8 + cp * 2 + 1] = u.y;
            }

        // ---- 5-level jammed halving butterfly over the 32 k-chunk lanes ----
        int n = 64;
#pragma unroll
        for (int m = 1; m < 32; m <<= 1) {
            n >>= 1;
            const bool hi = (lane & m) != 0;
#pragma unroll
            for (int i = 0; i < n; i++) {
                float send = hi ? v[i] : v[i + n];
                float keep = hi ? v[i + n] : v[i];
                v[i] = keep + __shfl_xor_sync(0xffffffffu, send, m);
            }
        }

        float r0 = tanhf(v[0] + xp.x);
        float r1 = tanhf(v[1] + xp.y);

        float* yp = y + ((size_t)b_out * Tsz + t) * (2 * Hsz) + (dir << 9) + colg;
        *(float2*)yp = make_float2(r0, r1);

        // ---- grid barrier (monotonic counter) ----
        __syncthreads();
        target += SCAN_CTAS;
        if (tid == 0) {
            __threadfence();
            unsigned vcnt = atomicAdd(&g_count, 1u) + 1u;
            if (vcnt != target) {
                volatile unsigned* vc = &g_count;
                while (*vc < target) { }
            }
            __threadfence();
        }
        __syncthreads();
    }
}

// ---------------------------------------------------------------------------
// Tail: hT_f = hs_f[T-1], hT_b = hs_b[t=0]
// ---------------------------------------------------------------------------
__global__ void tail_kernel(float* __restrict__ out)
{
    const int b = blockIdx.x;
    const int k = threadIdx.x;
    const float* y = out;
    const size_t yN = (size_t)Bsz * Tsz * 2 * Hsz;
    out[yN + (size_t)b * Hsz + k] =
        y[((size_t)b * Tsz + (Tsz - 1)) * (2 * Hsz) + k];
    out[yN + (size_t)Bsz * Hsz + (size_t)b * Hsz + k] =
        y[((size_t)b * Tsz) * (2 * Hsz) + Hsz + k];
}

// ---------------------------------------------------------------------------
extern "C" void kernel_launch(void* const* d_in, const int* in_sizes, int n_in,
                              void* d_out, int out_size)
{
    const float* x     = (const float*)d_in[0];
    const float* h0f   = (const float*)d_in[1];
    const float* h0b   = (const float*)d_in[2];
    const float* Wxf_w = (const float*)d_in[3];
    const float* Wxf_b = (const float*)d_in[4];
    const float* Whf_w = (const float*)d_in[5];
    const float* Wxb_w = (const float*)d_in[6];
    const float* Wxb_b = (const float*)d_in[7];
    const float* Whb_w = (const float*)d_in[8];
    float* out = (float*)d_out;

    const int scan_smem = (32 * WCH + 32 * HCH) * (int)sizeof(float);  // 148480 B
    cudaFuncSetAttribute(scan_kernel,
                         cudaFuncAttributeMaxDynamicSharedMemorySize, scan_smem);

    reset_bar_kernel<<<1, 1>>>();

    dim3 ggrid(4, 256, 2);
    xproj_gemm_kernel<<<ggrid, 256>>>(x, Wxf_w, Wxf_b, Wxb_w, Wxb_b);

    scan_kernel<<<SCAN_CTAS, 256, scan_smem>>>(h0f, h0b, Whf_w, Whb_w, out);

    tail_kernel<<<Bsz, Hsz>>>(out);
}